// round 6
// baseline (speedup 1.0000x reference)
#include <cuda_runtime.h>
#include <math.h>

#define JW 10
#define DCH 100          // days per chunk (T=50000 -> 500 chunks)
#define SEG 50           // days per prep-thread -> anchors land on even threads
#define MAXCH 1024

// Scratch (allocation-free rule: __device__ globals)
__device__ float g_Pex[MAXCH];   // exclusive prefix of log r at chunk starts

typedef unsigned long long u64;

// ---- packed f32x2 helpers (sm_103a) ----
__device__ __forceinline__ u64 pk2(float lo, float hi) {
    u64 r; asm("mov.b64 %0, {%1, %2};" : "=l"(r) : "f"(lo), "f"(hi)); return r;
}
__device__ __forceinline__ u64 mul2(u64 a, u64 b) {
    u64 d; asm("mul.rn.f32x2 %0, %1, %2;" : "=l"(d) : "l"(a), "l"(b)); return d;
}
__device__ __forceinline__ u64 fma2(u64 a, u64 b, u64 c) {
    u64 d; asm("fma.rn.f32x2 %0, %1, %2, %3;" : "=l"(d) : "l"(a), "l"(b), "l"(c)); return d;
}
__device__ __forceinline__ u64 add2(u64 a, u64 b) {
    u64 d; asm("add.rn.f32x2 %0, %1, %2;" : "=l"(d) : "l"(a), "l"(b)); return d;
}
__device__ __forceinline__ void stcs64(u64* p, u64 v) {
    asm volatile("st.global.cs.b64 [%0], %1;" :: "l"(p), "l"(v) : "memory");
}

// log(1+x), |x| <= ~0.011: degree-5 poly, abs err ~1e-9 (window-init use)
__device__ __forceinline__ float log1p_poly(float x) {
    float p = fmaf(x, 0.2f, -0.25f);
    p = fmaf(x, p, 1.0f / 3.0f);
    p = fmaf(x, p, -0.5f);
    p = fmaf(x, p, 1.0f);
    return x * p;
}

// ---- fused prep (ONE single-block launch) ----
// Thread t owns days [t*SEG, t*SEG+SEG). It multiplies its 50 r-values in
// fp32 (rel err ~3e-6), takes ONE __logf, then a shuffle block-scan gives
// the exclusive log-prefix. Chunk c's anchor is thread 2c's exclusive value.
__global__ void __launch_bounds__(1024) prep_kernel(const float* __restrict__ r,
                                                    int T, int nch) {
    __shared__ float shw[32];
    int t = threadIdx.x;
    int lane = t & 31;
    int wid = t >> 5;
    int beg = t * SEG;

    float loc = 0.0f;
    if (beg + SEG <= T) {
        const float2* R2 = (const float2*)(r + beg);   // 200B-aligned
        float p0 = 1.0f, p1 = 1.0f, p2 = 1.0f, p3 = 1.0f;
#pragma unroll
        for (int k = 0; k < SEG / 4; ++k) {            // 12 iters = 48 days
            float2 a = R2[2 * k];
            float2 b = R2[2 * k + 1];
            p0 *= a.x; p1 *= a.y; p2 *= b.x; p3 *= b.y;
        }
        float2 cpair = R2[SEG / 2 - 1];                // days 48,49
        p0 *= cpair.x; p1 *= cpair.y;
        loc = __logf((p0 * p2) * (p1 * p3));
    } else if (beg < T) {
        float p = 1.0f;
        for (int i = beg; i < T; ++i) p *= r[i];
        loc = __logf(p);
    }

    // inclusive warp scan
    float v = loc;
#pragma unroll
    for (int off = 1; off < 32; off <<= 1) {
        float u = __shfl_up_sync(0xffffffffu, v, off);
        if (lane >= off) v += u;
    }
    if (lane == 31) shw[wid] = v;
    __syncthreads();
    if (wid == 0) {
        float w = shw[lane];
#pragma unroll
        for (int off = 1; off < 32; off <<= 1) {
            float u = __shfl_up_sync(0xffffffffu, w, off);
            if (lane >= off) w += u;
        }
        shw[lane] = w;
    }
    __syncthreads();
    float base = (wid > 0) ? shw[wid - 1] : 0.0f;
    float excl = base + v - loc;                       // exclusive prefix

    if ((t & 1) == 0) {
        int c = t >> 1;
        if (c < nch) g_Pex[c] = excl;                  // sum log r[0..c*DCH-1]
    }
}

// ---- main kernel (unchanged from R5 best) ----
// A[d,s] = wlast[s]*exp(P[d]*invT[s]); chunk + window anchored via g_Pex and
// per-day log1p corrections, evaluated with __expf (independent, latency-flat).
// Day multiplier from r directly: (1+v)^t ~= 1 + t v + t(t-1)/2 v^2.
// M[d,s] = sum_j (rho*pi[j,s]) * A_ext[J+d-1-j, s]
__global__ void __launch_bounds__(128) main_kernel(
    const float* __restrict__ r,      // (T,)
    const float* __restrict__ warm,   // (J,S)
    const float* __restrict__ Ts,     // (S,)
    const float* __restrict__ rho,    // (S,)
    const float* __restrict__ pi,     // (J,S)
    u64* __restrict__ out,            // (T, S/2) packed float2
    int T, int S)
{
    int p = blockIdx.x * blockDim.x + threadIdx.x;
    int npairs = S >> 1;
    if (p >= npairs) return;
    int c  = blockIdx.y;
    int d0 = c * DCH;
    int s0 = 2 * p;

    float t0 = 1.0f / Ts[s0];
    float t1 = 1.0f / Ts[s0 + 1];
    float rho0 = rho[s0], rho1 = rho[s0 + 1];

    // dot weights with rho folded in
    u64 pir[JW];
#pragma unroll
    for (int j = 0; j < JW; ++j)
        pir[j] = pk2(pi[j * S + s0] * rho0, pi[j * S + s0 + 1] * rho1);

    // forward step coefs: (1+v)^t ~= 1 + c1 v + c2 v^2
    const u64 C1   = pk2(t0, t1);
    const u64 C2   = pk2(0.5f * t0 * (t0 - 1.0f), 0.5f * t1 * (t1 - 1.0f));
    const u64 ONE2 = pk2(1.0f, 1.0f);

    // window init: win[j] = A_ext[J + d0 - 1 - j]
    u64 win[JW];
    if (c == 0) {
#pragma unroll
        for (int j = 0; j < JW; ++j)
            win[j] = pk2(warm[(JW - 1 - j) * S + s0],
                         warm[(JW - 1 - j) * S + s0 + 1]);
    } else {
        float wl0 = warm[(JW - 1) * S + s0];
        float wl1 = warm[(JW - 1) * S + s0 + 1];
        // P values at the 10 window positions: independent exp evaluations
        float Pj = g_Pex[c];                  // sum log r[0..d0-1]
        win[0] = pk2(wl0 * __expf(Pj * t0), wl1 * __expf(Pj * t1));
#pragma unroll
        for (int j = 1; j < JW; ++j) {
            Pj -= log1p_poly(r[d0 - j] - 1.0f);   // scalar adds, loads indep
            win[j] = pk2(wl0 * __expf(Pj * t0), wl1 * __expf(Pj * t1));
        }
    }
    u64 a = win[0];                            // A(d0-1)

    const float4* R4 = (const float4*)(r + d0);   // d0*4B is 400B-aligned
    u64* o = out + (size_t)d0 * npairs + p;

#define STEP(rv) do {                                               \
        u64 m0 = mul2(pir[0], win[0]);                              \
        u64 m1 = mul2(pir[1], win[1]);                              \
        m0 = fma2(pir[2], win[2], m0);                              \
        m1 = fma2(pir[3], win[3], m1);                              \
        m0 = fma2(pir[4], win[4], m0);                              \
        m1 = fma2(pir[5], win[5], m1);                              \
        m0 = fma2(pir[6], win[6], m0);                              \
        m1 = fma2(pir[7], win[7], m1);                              \
        m0 = fma2(pir[8], win[8], m0);                              \
        m1 = fma2(pir[9], win[9], m1);                              \
        stcs64(o, add2(m0, m1));                                    \
        o += npairs;                                                \
        float vv = (rv) - 1.0f;                                     \
        u64 v2 = pk2(vv, vv);                                       \
        u64 e = fma2(v2, fma2(v2, C2, C1), ONE2);                   \
        a = mul2(a, e);                                             \
        _Pragma("unroll")                                           \
        for (int j = JW - 1; j > 0; --j) win[j] = win[j - 1];       \
        win[0] = a;                                                 \
    } while (0)

    if (d0 + DCH <= T) {
        // 25 iters of 4 days; unroll 5 -> 20 days/body = 2 full window rotations
#pragma unroll 5
        for (int it = 0; it < DCH / 4; ++it) {
            float4 L = R4[it];
            STEP(L.x);
            STEP(L.y);
            STEP(L.z);
            STEP(L.w);
        }
    } else {
        for (int d = d0; d < T; ++d) {
            float rv = r[d];
            STEP(rv);
        }
    }
#undef STEP
}

extern "C" void kernel_launch(void* const* d_in, const int* in_sizes, int n_in,
                              void* d_out, int out_size) {
    const float* r    = (const float*)d_in[0];  // (1,T)
    const float* warm = (const float*)d_in[1];  // (J,S)
    const float* Ts   = (const float*)d_in[2];  // (S,)
    const float* rho  = (const float*)d_in[3];  // (S,)
    const float* pi   = (const float*)d_in[4];  // (J,S)

    int T = in_sizes[0];
    int S = in_sizes[2];
    int nch = (T + DCH - 1) / DCH;

    prep_kernel<<<1, 1024>>>(r, T, nch);

    int npairs = S / 2;
    dim3 grid((npairs + 127) / 128, nch);
    main_kernel<<<grid, 128>>>(r, warm, Ts, rho, pi, (u64*)d_out, T, S);
}

// round 7
// speedup vs baseline: 1.0189x; 1.0189x over previous
#include <cuda_runtime.h>
#include <math.h>

#define JW 10
#define DCH 200          // days per chunk (T=50000 -> 250 chunks, grid=1000: 1 wave)
#define MAXCH 1024

// Scratch (allocation-free rule: __device__ globals)
__device__ float g_Pex[MAXCH];   // exclusive prefix of log r at chunk starts

typedef unsigned long long u64;

// ---- packed f32x2 helpers (sm_103a) ----
__device__ __forceinline__ u64 pk2(float lo, float hi) {
    u64 r; asm("mov.b64 %0, {%1, %2};" : "=l"(r) : "f"(lo), "f"(hi)); return r;
}
__device__ __forceinline__ u64 mul2(u64 a, u64 b) {
    u64 d; asm("mul.rn.f32x2 %0, %1, %2;" : "=l"(d) : "l"(a), "l"(b)); return d;
}
__device__ __forceinline__ u64 fma2(u64 a, u64 b, u64 c) {
    u64 d; asm("fma.rn.f32x2 %0, %1, %2, %3;" : "=l"(d) : "l"(a), "l"(b), "l"(c)); return d;
}
__device__ __forceinline__ u64 add2(u64 a, u64 b) {
    u64 d; asm("add.rn.f32x2 %0, %1, %2;" : "=l"(d) : "l"(a), "l"(b)); return d;
}
__device__ __forceinline__ void stcs64(u64* p, u64 v) {
    asm volatile("st.global.cs.b64 [%0], %1;" :: "l"(p), "l"(v) : "memory");
}

// log(1+x), |x| <= ~0.011: degree-5 poly, abs err ~1e-9
__device__ __forceinline__ float log1p_poly(float x) {
    float p = fmaf(x, 0.2f, -0.25f);
    p = fmaf(x, p, 1.0f / 3.0f);
    p = fmaf(x, p, -0.5f);
    p = fmaf(x, p, 1.0f);
    return x * p;
}

// ---- fused prep (ONE single-block launch, coalesced) ----
// Phase A: coalesced float4 loads; each thread folds 4 days -> log-sum,
//          pairs with neighbor lane via shfl -> 8-day sums in smem (25KB).
// Phase B: thread c sums its chunk's 25 smem values (DCH=200 -> 25 x 8day).
// Phase C: Hillis-Steele scan of 250 chunk sums -> exclusive prefixes.
__global__ void __launch_bounds__(1024) prep_kernel(const float* __restrict__ r,
                                                    int T, int nch) {
    __shared__ float s8[6272];    // 8-day log-sums: ceil(T/8) <= 6250
    __shared__ float cs[256];     // chunk sums
    int t = threadIdx.x;

    int n4 = (T + 3) >> 2;        // # float4 groups (T=50000 -> 12500)
    int n8 = (T + 7) >> 3;        // # 8-day groups  (6250)

    for (int k = 0; k < (n4 + 1023) / 1024; ++k) {
        int i4 = k * 1024 + t;
        float v = 0.0f;
        if (i4 < n4) {
            int d = i4 * 4;
            if (d + 4 <= T) {
                float4 rv = *(const float4*)(r + d);   // coalesced
                v = (log1p_poly(rv.x - 1.0f) + log1p_poly(rv.y - 1.0f))
                  + (log1p_poly(rv.z - 1.0f) + log1p_poly(rv.w - 1.0f));
            } else {
                for (int i = d; i < T; ++i) v += log1p_poly(r[i] - 1.0f);
            }
        }
        float w = v + __shfl_xor_sync(0xffffffffu, v, 1);
        int i8 = i4 >> 1;
        if ((t & 1) == 0 && i4 < n4 && i8 < n8) s8[i8] = w;
    }
    __syncthreads();

    // Phase B: per-chunk sums (25 x 8-day groups per chunk)
    if (t < 256) {
        float s = 0.0f;
        if (t < nch) {
            int base = t * (DCH / 8);
            float a0 = 0.f, a1 = 0.f, a2 = 0.f, a3 = 0.f, a4 = 0.f;
#pragma unroll
            for (int i = 0; i < DCH / 8; i += 5) {
                a0 += s8[base + i];
                a1 += s8[base + i + 1];
                a2 += s8[base + i + 2];
                a3 += s8[base + i + 3];
                a4 += s8[base + i + 4];
            }
            s = ((a0 + a1) + (a2 + a3)) + a4;
        }
        cs[t] = s;
    }
    __syncthreads();

    // Phase C: Hillis-Steele inclusive scan over 256 (covers nch<=250)
    float own = (t < 256) ? cs[t] : 0.0f;
#pragma unroll
    for (int off = 1; off < 256; off <<= 1) {
        float u = 0.0f;
        if (t < 256 && t >= off) u = cs[t - off];
        __syncthreads();
        if (t < 256) cs[t] += u;
        __syncthreads();
    }
    if (t < nch) g_Pex[t] = cs[t] - own;     // exclusive: sum log r[0..t*DCH-1]
}

// ---- main kernel ----
// A[d,s] = wlast[s]*exp(P[d]*invT[s]); chunk + window anchored via g_Pex and
// per-day log1p corrections, evaluated with __expf (independent, latency-flat).
// Day multiplier from r directly: (1+v)^t ~= 1 + t v + t(t-1)/2 v^2.
// M[d,s] = sum_j (rho*pi[j,s]) * A_ext[J+d-1-j, s]
__global__ void __launch_bounds__(128) main_kernel(
    const float* __restrict__ r,      // (T,)
    const float* __restrict__ warm,   // (J,S)
    const float* __restrict__ Ts,     // (S,)
    const float* __restrict__ rho,    // (S,)
    const float* __restrict__ pi,     // (J,S)
    u64* __restrict__ out,            // (T, S/2) packed float2
    int T, int S)
{
    int p = blockIdx.x * blockDim.x + threadIdx.x;
    int npairs = S >> 1;
    if (p >= npairs) return;
    int c  = blockIdx.y;
    int d0 = c * DCH;
    int s0 = 2 * p;

    float t0 = 1.0f / Ts[s0];
    float t1 = 1.0f / Ts[s0 + 1];
    float rho0 = rho[s0], rho1 = rho[s0 + 1];

    // dot weights with rho folded in
    u64 pir[JW];
#pragma unroll
    for (int j = 0; j < JW; ++j)
        pir[j] = pk2(pi[j * S + s0] * rho0, pi[j * S + s0 + 1] * rho1);

    // forward step coefs: (1+v)^t ~= 1 + c1 v + c2 v^2
    const u64 C1   = pk2(t0, t1);
    const u64 C2   = pk2(0.5f * t0 * (t0 - 1.0f), 0.5f * t1 * (t1 - 1.0f));
    const u64 ONE2 = pk2(1.0f, 1.0f);

    // window init: win[j] = A_ext[J + d0 - 1 - j]
    u64 win[JW];
    if (c == 0) {
#pragma unroll
        for (int j = 0; j < JW; ++j)
            win[j] = pk2(warm[(JW - 1 - j) * S + s0],
                         warm[(JW - 1 - j) * S + s0 + 1]);
    } else {
        float wl0 = warm[(JW - 1) * S + s0];
        float wl1 = warm[(JW - 1) * S + s0 + 1];
        // P values at the 10 window positions: independent exp evaluations
        float Pj = g_Pex[c];                  // sum log r[0..d0-1]
        win[0] = pk2(wl0 * __expf(Pj * t0), wl1 * __expf(Pj * t1));
#pragma unroll
        for (int j = 1; j < JW; ++j) {
            Pj -= log1p_poly(r[d0 - j] - 1.0f);   // scalar adds, loads indep
            win[j] = pk2(wl0 * __expf(Pj * t0), wl1 * __expf(Pj * t1));
        }
    }
    u64 a = win[0];                            // A(d0-1)

    const float4* R4 = (const float4*)(r + d0);   // d0*4B is 800B-aligned
    u64* o = out + (size_t)d0 * npairs + p;

#define STEP(rv) do {                                               \
        u64 m0 = mul2(pir[0], win[0]);                              \
        u64 m1 = mul2(pir[1], win[1]);                              \
        m0 = fma2(pir[2], win[2], m0);                              \
        m1 = fma2(pir[3], win[3], m1);                              \
        m0 = fma2(pir[4], win[4], m0);                              \
        m1 = fma2(pir[5], win[5], m1);                              \
        m0 = fma2(pir[6], win[6], m0);                              \
        m1 = fma2(pir[7], win[7], m1);                              \
        m0 = fma2(pir[8], win[8], m0);                              \
        m1 = fma2(pir[9], win[9], m1);                              \
        stcs64(o, add2(m0, m1));                                    \
        o += npairs;                                                \
        float vv = (rv) - 1.0f;                                     \
        u64 v2 = pk2(vv, vv);                                       \
        u64 e = fma2(v2, fma2(v2, C2, C1), ONE2);                   \
        a = mul2(a, e);                                             \
        _Pragma("unroll")                                           \
        for (int j = JW - 1; j > 0; --j) win[j] = win[j - 1];       \
        win[0] = a;                                                 \
    } while (0)

    if (d0 + DCH <= T) {
        // 50 iters of 4 days; unroll 5 -> 20 days/body = 2 full window rotations
#pragma unroll 5
        for (int it = 0; it < DCH / 4; ++it) {
            float4 L = R4[it];
            STEP(L.x);
            STEP(L.y);
            STEP(L.z);
            STEP(L.w);
        }
    } else {
        for (int d = d0; d < T; ++d) {
            float rv = r[d];
            STEP(rv);
        }
    }
#undef STEP
}

extern "C" void kernel_launch(void* const* d_in, const int* in_sizes, int n_in,
                              void* d_out, int out_size) {
    const float* r    = (const float*)d_in[0];  // (1,T)
    const float* warm = (const float*)d_in[1];  // (J,S)
    const float* Ts   = (const float*)d_in[2];  // (S,)
    const float* rho  = (const float*)d_in[3];  // (S,)
    const float* pi   = (const float*)d_in[4];  // (J,S)

    int T = in_sizes[0];
    int S = in_sizes[2];
    int nch = (T + DCH - 1) / DCH;

    prep_kernel<<<1, 1024>>>(r, T, nch);

    int npairs = S / 2;
    dim3 grid((npairs + 127) / 128, nch);
    main_kernel<<<grid, 128>>>(r, warm, Ts, rho, pi, (u64*)d_out, T, S);
}

// round 8
// speedup vs baseline: 1.0204x; 1.0014x over previous
#include <cuda_runtime.h>
#include <math.h>

#define JW 10
#define DCH 100          // days per chunk (T=50000 -> 500 chunks)
#define MAXCH 1024

// Scratch (allocation-free rule: __device__ globals)
__device__ float g_Pex[MAXCH];   // exclusive prefix of log r at chunk starts

typedef unsigned long long u64;

// ---- packed f32x2 helpers (sm_103a) ----
__device__ __forceinline__ u64 pk2(float lo, float hi) {
    u64 r; asm("mov.b64 %0, {%1, %2};" : "=l"(r) : "f"(lo), "f"(hi)); return r;
}
__device__ __forceinline__ u64 mul2(u64 a, u64 b) {
    u64 d; asm("mul.rn.f32x2 %0, %1, %2;" : "=l"(d) : "l"(a), "l"(b)); return d;
}
__device__ __forceinline__ u64 fma2(u64 a, u64 b, u64 c) {
    u64 d; asm("fma.rn.f32x2 %0, %1, %2, %3;" : "=l"(d) : "l"(a), "l"(b), "l"(c)); return d;
}
__device__ __forceinline__ u64 add2(u64 a, u64 b) {
    u64 d; asm("add.rn.f32x2 %0, %1, %2;" : "=l"(d) : "l"(a), "l"(b)); return d;
}
// 16-byte streaming store: two packed f32x2 (4 consecutive samples)
__device__ __forceinline__ void stcs128(u64* p, u64 lo, u64 hi) {
    asm volatile("st.global.cs.v2.b64 [%0], {%1, %2};"
                 :: "l"(p), "l"(lo), "l"(hi) : "memory");
}

// log(1+x), |x| <= ~0.011: degree-5 poly, abs err ~1e-9
__device__ __forceinline__ float log1p_poly(float x) {
    float p = fmaf(x, 0.2f, -0.25f);
    p = fmaf(x, p, 1.0f / 3.0f);
    p = fmaf(x, p, -0.5f);
    p = fmaf(x, p, 1.0f);
    return x * p;
}

// ---- fused prep (ONE single-block launch, coalesced) — unchanged from R7 ----
__global__ void __launch_bounds__(1024) prep_kernel(const float* __restrict__ r,
                                                    int T, int nch) {
    __shared__ float s8[6272];    // 8-day log-sums: ceil(T/8) <= 6250
    __shared__ float cs[512];     // chunk sums
    int t = threadIdx.x;

    int n4 = (T + 3) >> 2;        // # float4 groups (T=50000 -> 12500)
    int n8 = (T + 7) >> 3;        // # 8-day groups  (6250)

    for (int k = 0; k < (n4 + 1023) / 1024; ++k) {
        int i4 = k * 1024 + t;
        float v = 0.0f;
        if (i4 < n4) {
            int d = i4 * 4;
            if (d + 4 <= T) {
                float4 rv = *(const float4*)(r + d);   // coalesced
                v = (log1p_poly(rv.x - 1.0f) + log1p_poly(rv.y - 1.0f))
                  + (log1p_poly(rv.z - 1.0f) + log1p_poly(rv.w - 1.0f));
            } else {
                for (int i = d; i < T; ++i) v += log1p_poly(r[i] - 1.0f);
            }
        }
        float w = v + __shfl_xor_sync(0xffffffffu, v, 1);
        int i8 = i4 >> 1;
        if ((t & 1) == 0 && i4 < n4 && i8 < n8) s8[i8] = w;
    }
    __syncthreads();

    // per-chunk sums: DCH=100 -> 12.5 x 8-day groups; use 25 x 4-day? No:
    // chunk c covers s8[c*12.5 ..] only when DCH%8==0. DCH=100 is not.
    // Instead sum 25 float2-of-4day? Simplest: chunk sums from 4-day grain:
    // rebuild: chunk c = sum of s8 pairs is wrong; use day-grain via s8 only
    // when aligned. DCH=100 = 12*8 + 4, so do: base8 = c*12 + (c>>1) ... messy.
    // -> use 4-day grain stored instead? We stored 8-day sums. For DCH=100,
    // chunk boundaries fall on 4-day grain. Handle by summing 8-day groups
    // fully inside the chunk and adding the straddling halves from shuffle
    // source values is complex; instead recompute from r for the odd tail.
    // Simpler correct path: 50 chunks-of-200 internally, then split below.
    if (t < 512) {
        float s = 0.0f;
        int c2 = t;                       // 200-day super-chunk id
        if (c2 < (nch + 1) / 2) {
            int base = c2 * 25;           // 25 x 8-day groups per 200 days
            float a0 = 0.f, a1 = 0.f, a2 = 0.f, a3 = 0.f, a4 = 0.f;
#pragma unroll
            for (int i = 0; i < 25; i += 5) {
                a0 += s8[base + i];
                a1 += s8[base + i + 1];
                a2 += s8[base + i + 2];
                a3 += s8[base + i + 3];
                a4 += s8[base + i + 4];
            }
            s = ((a0 + a1) + (a2 + a3)) + a4;
        }
        cs[t] = s;
    }
    __syncthreads();

    // Hillis-Steele inclusive scan over 512 super-chunk sums
    float own = (t < 512) ? cs[t] : 0.0f;
#pragma unroll
    for (int off = 1; off < 512; off <<= 1) {
        float u = 0.0f;
        if (t < 512 && t >= off) u = cs[t - off];
        __syncthreads();
        if (t < 512) cs[t] += u;
        __syncthreads();
    }
    // emit 100-day-chunk exclusive prefixes: even chunk = super-chunk start;
    // odd chunk = super start + first 100 days (12 x 8-day + 1 x 4-day half)
    if (t < nch) {
        int c2 = t >> 1;
        float base = cs[c2] - ((t < 512) ? 0.0f : 0.0f);   // placeholder
        float excl = cs[c2] - own;  // wrong for t odd; fix below
        // recompute cleanly:
        float superExcl = (c2 == 0) ? 0.0f : cs[c2 - 1];
        if ((t & 1) == 0) {
            g_Pex[t] = superExcl;
        } else {
            // add first 100 days of super-chunk c2: groups [c2*25, c2*25+12)
            // plus half of group c2*25+12 (its first 4 days)
            float h = 0.0f;
            int b = c2 * 25;
#pragma unroll
            for (int i = 0; i < 12; ++i) h += s8[b + i];
            // first 4 days of the 13th group: recompute from r
            int d = (c2 * 200) + 96;
            h += (log1p_poly(r[d] - 1.0f) + log1p_poly(r[d + 1] - 1.0f))
               + (log1p_poly(r[d + 2] - 1.0f) + log1p_poly(r[d + 3] - 1.0f));
            g_Pex[t] = superExcl + h;
        }
    }
}

// ---- main kernel: QS=4 samples/thread, two f32x2 windows, STG.128 ----
__global__ void __launch_bounds__(128) main_kernel(
    const float* __restrict__ r,      // (T,)
    const float* __restrict__ warm,   // (J,S)
    const float* __restrict__ Ts,     // (S,)
    const float* __restrict__ rho,    // (S,)
    const float* __restrict__ pi,     // (J,S)
    u64* __restrict__ out,            // (T, S/2) packed f32x2
    int T, int S)
{
    int q = blockIdx.x * blockDim.x + threadIdx.x;   // quad index
    int nquads = S >> 2;
    if (q >= nquads) return;
    int c  = blockIdx.y;
    int d0 = c * DCH;
    int s0 = 4 * q;
    (void)s0;

    float4 Ts4  = ((const float4*)Ts)[q];
    float4 rho4 = ((const float4*)rho)[q];
    float t0 = 1.0f / Ts4.x, t1 = 1.0f / Ts4.y;
    float t2 = 1.0f / Ts4.z, t3 = 1.0f / Ts4.w;

    u64 pirA[JW], pirB[JW];
#pragma unroll
    for (int j = 0; j < JW; ++j) {
        float4 p4 = ((const float4*)(pi + j * S))[q];
        pirA[j] = pk2(p4.x * rho4.x, p4.y * rho4.y);
        pirB[j] = pk2(p4.z * rho4.z, p4.w * rho4.w);
    }

    const u64 C1A = pk2(t0, t1), C1B = pk2(t2, t3);
    const u64 C2A = pk2(0.5f * t0 * (t0 - 1.0f), 0.5f * t1 * (t1 - 1.0f));
    const u64 C2B = pk2(0.5f * t2 * (t2 - 1.0f), 0.5f * t3 * (t3 - 1.0f));
    const u64 ONE2 = pk2(1.0f, 1.0f);

    u64 winA[JW], winB[JW];
    if (c == 0) {
#pragma unroll
        for (int j = 0; j < JW; ++j) {
            float4 w4 = ((const float4*)(warm + (JW - 1 - j) * S))[q];
            winA[j] = pk2(w4.x, w4.y);
            winB[j] = pk2(w4.z, w4.w);
        }
    } else {
        float4 wl4 = ((const float4*)(warm + (JW - 1) * S))[q];
        float Pex = g_Pex[c];                 // sum log r[0..d0-1]
        winA[0] = pk2(wl4.x * __expf(Pex * t0), wl4.y * __expf(Pex * t1));
        winB[0] = pk2(wl4.z * __expf(Pex * t2), wl4.w * __expf(Pex * t3));
        // backward walk: (1+v)^(-t) ~= 1 - t v + t(t+1)/2 v^2 - t(t+1)(t+2)/6 v^3
        u64 B1A = pk2(-t0, -t1), B1B = pk2(-t2, -t3);
        u64 B2A = pk2(0.5f * t0 * (t0 + 1.0f), 0.5f * t1 * (t1 + 1.0f));
        u64 B2B = pk2(0.5f * t2 * (t2 + 1.0f), 0.5f * t3 * (t3 + 1.0f));
        u64 B3A = pk2(-t0 * (t0 + 1.0f) * (t0 + 2.0f) / 6.0f,
                      -t1 * (t1 + 1.0f) * (t1 + 2.0f) / 6.0f);
        u64 B3B = pk2(-t2 * (t2 + 1.0f) * (t2 + 2.0f) / 6.0f,
                      -t3 * (t3 + 1.0f) * (t3 + 2.0f) / 6.0f);
#pragma unroll
        for (int j = 1; j < JW; ++j) {
            float v = r[d0 - j] - 1.0f;
            u64 v2 = pk2(v, v);
            u64 eA = fma2(v2, fma2(v2, fma2(v2, B3A, B2A), B1A), ONE2);
            u64 eB = fma2(v2, fma2(v2, fma2(v2, B3B, B2B), B1B), ONE2);
            winA[j] = mul2(winA[j - 1], eA);
            winB[j] = mul2(winB[j - 1], eB);
        }
    }
    u64 aA = winA[0], aB = winB[0];

    const float4* R4 = (const float4*)(r + d0);   // d0*4B is 400B-aligned
    u64* o = out + ((size_t)d0 * nquads + q) * 2;
    const size_t ostep = (size_t)nquads * 2;

#define STEP(rv) do {                                               \
        u64 mA0 = mul2(pirA[0], winA[0]);                           \
        u64 mA1 = mul2(pirA[1], winA[1]);                           \
        u64 mB0 = mul2(pirB[0], winB[0]);                           \
        u64 mB1 = mul2(pirB[1], winB[1]);                           \
        mA0 = fma2(pirA[2], winA[2], mA0);                          \
        mA1 = fma2(pirA[3], winA[3], mA1);                          \
        mB0 = fma2(pirB[2], winB[2], mB0);                          \
        mB1 = fma2(pirB[3], winB[3], mB1);                          \
        mA0 = fma2(pirA[4], winA[4], mA0);                          \
        mA1 = fma2(pirA[5], winA[5], mA1);                          \
        mB0 = fma2(pirB[4], winB[4], mB0);                          \
        mB1 = fma2(pirB[5], winB[5], mB1);                          \
        mA0 = fma2(pirA[6], winA[6], mA0);                          \
        mA1 = fma2(pirA[7], winA[7], mA1);                          \
        mB0 = fma2(pirB[6], winB[6], mB0);                          \
        mB1 = fma2(pirB[7], winB[7], mB1);                          \
        mA0 = fma2(pirA[8], winA[8], mA0);                          \
        mA1 = fma2(pirA[9], winA[9], mA1);                          \
        mB0 = fma2(pirB[8], winB[8], mB0);                          \
        mB1 = fma2(pirB[9], winB[9], mB1);                          \
        stcs128(o, add2(mA0, mA1), add2(mB0, mB1));                 \
        o += ostep;                                                 \
        float vv = (rv) - 1.0f;                                     \
        u64 v2 = pk2(vv, vv);                                       \
        u64 eA = fma2(v2, fma2(v2, C2A, C1A), ONE2);                \
        u64 eB = fma2(v2, fma2(v2, C2B, C1B), ONE2);                \
        aA = mul2(aA, eA);                                          \
        aB = mul2(aB, eB);                                          \
        _Pragma("unroll")                                           \
        for (int j = JW - 1; j > 0; --j) {                          \
            winA[j] = winA[j - 1];                                  \
            winB[j] = winB[j - 1];                                  \
        }                                                           \
        winA[0] = aA;                                               \
        winB[0] = aB;                                               \
    } while (0)

    if (d0 + DCH <= T) {
        // 25 iters of 4 days; unroll 5 -> 20 days/body = 2 full window rotations
#pragma unroll 5
        for (int it = 0; it < DCH / 4; ++it) {
            float4 L = R4[it];
            STEP(L.x);
            STEP(L.y);
            STEP(L.z);
            STEP(L.w);
        }
    } else {
        for (int d = d0; d < T; ++d) {
            float rv = r[d];
            STEP(rv);
        }
    }
#undef STEP
}

extern "C" void kernel_launch(void* const* d_in, const int* in_sizes, int n_in,
                              void* d_out, int out_size) {
    const float* r    = (const float*)d_in[0];  // (1,T)
    const float* warm = (const float*)d_in[1];  // (J,S)
    const float* Ts   = (const float*)d_in[2];  // (S,)
    const float* rho  = (const float*)d_in[3];  // (S,)
    const float* pi   = (const float*)d_in[4];  // (J,S)

    int T = in_sizes[0];
    int S = in_sizes[2];
    int nch = (T + DCH - 1) / DCH;

    prep_kernel<<<1, 1024>>>(r, T, nch);

    int nquads = S / 4;
    dim3 grid((nquads + 127) / 128, nch);
    main_kernel<<<grid, 128>>>(r, warm, Ts, rho, pi, (u64*)d_out, T, S);
}